// round 2
// baseline (speedup 1.0000x reference)
#include <cuda_runtime.h>
#include <math.h>

// Problem constants
#define CB  2
#define CS  2048
#define CD  768
#define CH  12
#define CDK 64
#define CM  (CB * CS)            // 4096 rows for projections
#define BHS (CB * CH * CS)       // 49152 attention rows
#define OUT_ELEMS (CB * CS * CD) // 3145728 (output tensor), attn follows in d_out

// Scratch (static device allocations — no cudaMalloc allowed)
__device__ float  g_Q[CB * CH * CS * CDK];
__device__ float  g_K[CB * CH * CS * CDK];
__device__ float  g_V[CB * CH * CS * CDK];
__device__ float  g_ctx[CB * CH * CS * CDK];
__device__ float2 g_stats[BHS];

// ---------------------------------------------------------------------------
// Kernel 1: QKV projection.  out[b,h,s,dk] = sum_k X[b,s,k] * W[h*64+dk, k]
// Classic 128x128x8 SGEMM, 256 threads, 8x8 microtile.
// ---------------------------------------------------------------------------
__global__ void __launch_bounds__(256) proj_qkv_kernel(
    const float* __restrict__ X, const float* __restrict__ W,
    float* __restrict__ out)
{
    __shared__ float As[8][128];
    __shared__ float Bs[8][128];
    const int tid = threadIdx.x;
    const int tx = tid & 15, ty = tid >> 4;
    const int m0 = blockIdx.y * 128, n0 = blockIdx.x * 128;
    const int lr = tid >> 1;        // 0..127
    const int lc = (tid & 1) * 4;   // 0 or 4

    float acc[8][8];
#pragma unroll
    for (int i = 0; i < 8; i++)
#pragma unroll
        for (int j = 0; j < 8; j++) acc[i][j] = 0.f;

    const float* Ag = X + (m0 + lr) * CD + lc;
    const float* Bg = W + (n0 + lr) * CD + lc;

    for (int k0 = 0; k0 < CD; k0 += 8) {
        float4 av = *(const float4*)(Ag + k0);
        float4 bv = *(const float4*)(Bg + k0);
        __syncthreads();
        As[lc + 0][lr] = av.x; As[lc + 1][lr] = av.y;
        As[lc + 2][lr] = av.z; As[lc + 3][lr] = av.w;
        Bs[lc + 0][lr] = bv.x; Bs[lc + 1][lr] = bv.y;
        Bs[lc + 2][lr] = bv.z; Bs[lc + 3][lr] = bv.w;
        __syncthreads();
#pragma unroll
        for (int k = 0; k < 8; k++) {
            float a[8], b[8];
            *(float4*)&a[0] = *(const float4*)&As[k][ty * 8];
            *(float4*)&a[4] = *(const float4*)&As[k][ty * 8 + 4];
            *(float4*)&b[0] = *(const float4*)&Bs[k][tx * 8];
            *(float4*)&b[4] = *(const float4*)&Bs[k][tx * 8 + 4];
#pragma unroll
            for (int i = 0; i < 8; i++)
#pragma unroll
                for (int j = 0; j < 8; j++)
                    acc[i][j] += a[i] * b[j];
        }
    }

    // Scatter to [B,H,S,DK]
#pragma unroll
    for (int i = 0; i < 8; i++) {
        int m = m0 + ty * 8 + i;
        int b = m >> 11, s = m & (CS - 1);
#pragma unroll
        for (int j = 0; j < 8; j++) {
            int n = n0 + tx * 8 + j;
            int h = n >> 6, dk = n & 63;
            out[((b * CH + h) * CS + s) * CDK + dk] = acc[i][j];
        }
    }
}

// ---------------------------------------------------------------------------
// Kernel 2: scores = Q·K^T/8 + pos_bias, masked. Writes raw scores into the
// attn region of d_out. K dim = 64, processed in 8-wide shared tiles.
// ---------------------------------------------------------------------------
__global__ void __launch_bounds__(256) scores_kernel(
    const float* __restrict__ Q, const float* __restrict__ K,
    const float* __restrict__ pos_bias, const int* __restrict__ mask,
    float* __restrict__ raw)
{
    __shared__ float As[8][128];
    __shared__ float Bs[8][128];
    const int tid = threadIdx.x;
    const int tx = tid & 15, ty = tid >> 4;
    const int bh = blockIdx.z;
    const int b = bh / CH, h = bh - b * CH;
    const int q0 = blockIdx.y * 128, kk0 = blockIdx.x * 128;
    const int lr = tid >> 1;
    const int lc = (tid & 1) * 4;

    float acc[8][8];
#pragma unroll
    for (int i = 0; i < 8; i++)
#pragma unroll
        for (int j = 0; j < 8; j++) acc[i][j] = 0.f;

    const float* Qg = Q + (bh * CS + q0 + lr) * CDK + lc;
    const float* Kg = K + (bh * CS + kk0 + lr) * CDK + lc;

    for (int k0 = 0; k0 < CDK; k0 += 8) {
        float4 av = *(const float4*)(Qg + k0);
        float4 bv = *(const float4*)(Kg + k0);
        __syncthreads();
        As[lc + 0][lr] = av.x; As[lc + 1][lr] = av.y;
        As[lc + 2][lr] = av.z; As[lc + 3][lr] = av.w;
        Bs[lc + 0][lr] = bv.x; Bs[lc + 1][lr] = bv.y;
        Bs[lc + 2][lr] = bv.z; Bs[lc + 3][lr] = bv.w;
        __syncthreads();
#pragma unroll
        for (int k = 0; k < 8; k++) {
            float a[8], bb[8];
            *(float4*)&a[0]  = *(const float4*)&As[k][ty * 8];
            *(float4*)&a[4]  = *(const float4*)&As[k][ty * 8 + 4];
            *(float4*)&bb[0] = *(const float4*)&Bs[k][tx * 8];
            *(float4*)&bb[4] = *(const float4*)&Bs[k][tx * 8 + 4];
#pragma unroll
            for (int i = 0; i < 8; i++)
#pragma unroll
                for (int j = 0; j < 8; j++)
                    acc[i][j] += a[i] * bb[j];
        }
    }

    const int kc0 = kk0 + tx * 8;
#pragma unroll
    for (int i = 0; i < 8; i++) {
        int qq = q0 + ty * 8 + i;
        const float* pbr = pos_bias + (h * CS + qq) * CS + kc0;
        const int*   mkr = mask + (b * CS + qq) * CS + kc0;
        float*       rr  = raw + (bh * CS + qq) * CS + kc0;
        float4 p0 = *(const float4*)(pbr);
        float4 p1 = *(const float4*)(pbr + 4);
        int4   m0v = *(const int4*)(mkr);
        int4   m1v = *(const int4*)(mkr + 4);
        float4 o0, o1;
        o0.x = (m0v.x == 0) ? -1e9f : acc[i][0] * 0.125f + p0.x;
        o0.y = (m0v.y == 0) ? -1e9f : acc[i][1] * 0.125f + p0.y;
        o0.z = (m0v.z == 0) ? -1e9f : acc[i][2] * 0.125f + p0.z;
        o0.w = (m0v.w == 0) ? -1e9f : acc[i][3] * 0.125f + p0.w;
        o1.x = (m1v.x == 0) ? -1e9f : acc[i][4] * 0.125f + p1.x;
        o1.y = (m1v.y == 0) ? -1e9f : acc[i][5] * 0.125f + p1.y;
        o1.z = (m1v.z == 0) ? -1e9f : acc[i][6] * 0.125f + p1.z;
        o1.w = (m1v.w == 0) ? -1e9f : acc[i][7] * 0.125f + p1.w;
        *(float4*)(rr)     = o0;
        *(float4*)(rr + 4) = o1;
    }
}

// ---------------------------------------------------------------------------
// Kernel 3: per-row max and 1/sum(exp(s-max)).  One 256-thread block per row.
// ---------------------------------------------------------------------------
__global__ void __launch_bounds__(256) stats_kernel(
    const float* __restrict__ raw, float2* __restrict__ stats)
{
    __shared__ float red[256];
    const int r = blockIdx.x;
    const int tid = threadIdx.x;
    const float* p = raw + r * CS;

    float v[8];
    *(float4*)&v[0] = *(const float4*)(p + tid * 8);
    *(float4*)&v[4] = *(const float4*)(p + tid * 8 + 4);

    float mx = v[0];
#pragma unroll
    for (int i = 1; i < 8; i++) mx = fmaxf(mx, v[i]);
    red[tid] = mx;
    __syncthreads();
    for (int s = 128; s > 0; s >>= 1) {
        if (tid < s) red[tid] = fmaxf(red[tid], red[tid + s]);
        __syncthreads();
    }
    mx = red[0];
    __syncthreads();

    float se = 0.f;
#pragma unroll
    for (int i = 0; i < 8; i++) se += __expf(v[i] - mx);
    red[tid] = se;
    __syncthreads();
    for (int s = 128; s > 0; s >>= 1) {
        if (tid < s) red[tid] += red[tid + s];
        __syncthreads();
    }
    if (tid == 0) stats[r] = make_float2(mx, 1.f / red[0]);
}

// ---------------------------------------------------------------------------
// Kernel 4: normalize attn in place AND compute ctx = attn @ V.
// Block = (bh, 128 q-rows). 256 threads, 8x4 microtile over [128 x 64].
// ---------------------------------------------------------------------------
__global__ void __launch_bounds__(256) pv_kernel(
    float* __restrict__ attn, const float* __restrict__ V,
    const float2* __restrict__ stats, float* __restrict__ ctx)
{
    __shared__ float Ps[16][128];
    __shared__ float Vs[16][64];
    __shared__ float smax[128], sinv[128];
    const int tid = threadIdx.x;
    const int tx = tid & 15, ty = tid >> 4;
    const int bh = blockIdx.y;
    const int q0 = blockIdx.x * 128;

    if (tid < 128) {
        float2 st = stats[bh * CS + q0 + tid];
        smax[tid] = st.x;
        sinv[tid] = st.y;
    }
    __syncthreads();

    const int lr = tid >> 1;        // 0..127 (q row within tile)
    const int lc = (tid & 1) * 8;   // 0 or 8 (k offset within 16-tile)
    float* rowbase = attn + (bh * CS + q0) * CS;
    const float* Vb = V + bh * CS * CDK;
    const float myMax = smax[lr];
    const float myInv = sinv[lr];

    float acc[8][4];
#pragma unroll
    for (int i = 0; i < 8; i++)
#pragma unroll
        for (int j = 0; j < 4; j++) acc[i][j] = 0.f;

    const int vkr = tid >> 4;        // 0..15
    const int vng = (tid & 15) * 4;  // 0..60

    for (int k0 = 0; k0 < CS; k0 += 16) {
        float4 r0 = *(const float4*)(rowbase + lr * CS + k0 + lc);
        float4 r1 = *(const float4*)(rowbase + lr * CS + k0 + lc + 4);
        float4 p0, p1;
        p0.x = __expf(r0.x - myMax) * myInv;
        p0.y = __expf(r0.y - myMax) * myInv;
        p0.z = __expf(r0.z - myMax) * myInv;
        p0.w = __expf(r0.w - myMax) * myInv;
        p1.x = __expf(r1.x - myMax) * myInv;
        p1.y = __expf(r1.y - myMax) * myInv;
        p1.z = __expf(r1.z - myMax) * myInv;
        p1.w = __expf(r1.w - myMax) * myInv;
        // write normalized attn back (this is the final attn output)
        *(float4*)(rowbase + lr * CS + k0 + lc)     = p0;
        *(float4*)(rowbase + lr * CS + k0 + lc + 4) = p1;
        float4 vv = *(const float4*)(Vb + (k0 + vkr) * CDK + vng);
        __syncthreads();
        Ps[lc + 0][lr] = p0.x; Ps[lc + 1][lr] = p0.y;
        Ps[lc + 2][lr] = p0.z; Ps[lc + 3][lr] = p0.w;
        Ps[lc + 4][lr] = p1.x; Ps[lc + 5][lr] = p1.y;
        Ps[lc + 6][lr] = p1.z; Ps[lc + 7][lr] = p1.w;
        *(float4*)&Vs[vkr][vng] = vv;
        __syncthreads();
#pragma unroll
        for (int k = 0; k < 16; k++) {
            float a[8];
            *(float4*)&a[0] = *(const float4*)&Ps[k][ty * 8];
            *(float4*)&a[4] = *(const float4*)&Ps[k][ty * 8 + 4];
            float4 bv = *(const float4*)&Vs[k][tx * 4];
#pragma unroll
            for (int i = 0; i < 8; i++) {
                acc[i][0] += a[i] * bv.x;
                acc[i][1] += a[i] * bv.y;
                acc[i][2] += a[i] * bv.z;
                acc[i][3] += a[i] * bv.w;
            }
        }
    }

#pragma unroll
    for (int i = 0; i < 8; i++) {
        float4 o;
        o.x = acc[i][0]; o.y = acc[i][1]; o.z = acc[i][2]; o.w = acc[i][3];
        *(float4*)(ctx + (bh * CS + q0 + ty * 8 + i) * CDK + tx * 4) = o;
    }
}

// ---------------------------------------------------------------------------
// Kernel 5: output projection. out[b,s,n] = sum_d ctx[b,h(d),s,dk(d)]*Wo[n,d] + bo[n]
// ---------------------------------------------------------------------------
__global__ void __launch_bounds__(256) outproj_kernel(
    const float* __restrict__ ctx, const float* __restrict__ W,
    const float* __restrict__ bias, float* __restrict__ out)
{
    __shared__ float As[8][128];
    __shared__ float Bs[8][128];
    const int tid = threadIdx.x;
    const int tx = tid & 15, ty = tid >> 4;
    const int m0 = blockIdx.y * 128, n0 = blockIdx.x * 128;
    const int lr = tid >> 1;
    const int lc = (tid & 1) * 4;

    float acc[8][8];
#pragma unroll
    for (int i = 0; i < 8; i++)
#pragma unroll
        for (int j = 0; j < 8; j++) acc[i][j] = 0.f;

    const int mrow = m0 + lr;
    const int bb = mrow >> 11, ss = mrow & (CS - 1);
    const float* Abase = ctx + (bb * CH * CS + ss) * CDK;
    const float* Bg = W + (n0 + lr) * CD + lc;

    for (int k0 = 0; k0 < CD; k0 += 8) {
        int kk = k0 + lc;
        int h = kk >> 6, dk = kk & 63;
        float4 av = *(const float4*)(Abase + h * CS * CDK + dk);
        float4 bv = *(const float4*)(Bg + k0);
        __syncthreads();
        As[lc + 0][lr] = av.x; As[lc + 1][lr] = av.y;
        As[lc + 2][lr] = av.z; As[lc + 3][lr] = av.w;
        Bs[lc + 0][lr] = bv.x; Bs[lc + 1][lr] = bv.y;
        Bs[lc + 2][lr] = bv.z; Bs[lc + 3][lr] = bv.w;
        __syncthreads();
#pragma unroll
        for (int k = 0; k < 8; k++) {
            float a[8], b[8];
            *(float4*)&a[0] = *(const float4*)&As[k][ty * 8];
            *(float4*)&a[4] = *(const float4*)&As[k][ty * 8 + 4];
            *(float4*)&b[0] = *(const float4*)&Bs[k][tx * 8];
            *(float4*)&b[4] = *(const float4*)&Bs[k][tx * 8 + 4];
#pragma unroll
            for (int i = 0; i < 8; i++)
#pragma unroll
                for (int j = 0; j < 8; j++)
                    acc[i][j] += a[i] * b[j];
        }
    }

#pragma unroll
    for (int i = 0; i < 8; i++) {
        int m = m0 + ty * 8 + i;
#pragma unroll
        for (int j = 0; j < 8; j++) {
            int n = n0 + tx * 8 + j;
            out[m * CD + n] = acc[i][j] + bias[n];
        }
    }
}

// ---------------------------------------------------------------------------
extern "C" void kernel_launch(void* const* d_in, const int* in_sizes, int n_in,
                              void* d_out, int out_size)
{
    (void)in_sizes; (void)n_in; (void)out_size;
    const float* query    = (const float*)d_in[0];
    const float* key      = (const float*)d_in[1];
    const float* value    = (const float*)d_in[2];
    const int*   mask     = (const int*)d_in[3];
    const float* pos_bias = (const float*)d_in[4];
    const float* Wq       = (const float*)d_in[5];
    const float* Wk       = (const float*)d_in[6];
    const float* Wv       = (const float*)d_in[7];
    const float* Wo       = (const float*)d_in[8];
    const float* bo       = (const float*)d_in[9];

    float* out  = (float*)d_out;
    float* attn = out + OUT_ELEMS;

    float *pQ, *pK, *pV, *pC;
    float2* pSt;
    cudaGetSymbolAddress((void**)&pQ,  g_Q);
    cudaGetSymbolAddress((void**)&pK,  g_K);
    cudaGetSymbolAddress((void**)&pV,  g_V);
    cudaGetSymbolAddress((void**)&pC,  g_ctx);
    cudaGetSymbolAddress((void**)&pSt, g_stats);

    dim3 gProj(CD / 128, CM / 128);   // (6, 32)
    proj_qkv_kernel<<<gProj, 256>>>(query, Wq, pQ);
    proj_qkv_kernel<<<gProj, 256>>>(key,   Wk, pK);
    proj_qkv_kernel<<<gProj, 256>>>(value, Wv, pV);

    dim3 gScores(CS / 128, CS / 128, CB * CH);  // (16,16,24)
    scores_kernel<<<gScores, 256>>>(pQ, pK, pos_bias, mask, attn);

    stats_kernel<<<BHS, 256>>>(attn, pSt);

    dim3 gPV(CS / 128, CB * CH);      // (16, 24)
    pv_kernel<<<gPV, 256>>>(attn, pV, pSt, pC);

    outproj_kernel<<<gProj, 256>>>(pC, Wo, bo, out);
}

// round 5
// speedup vs baseline: 1.6260x; 1.6260x over previous
#include <cuda_runtime.h>
#include <cuda_bf16.h>

#define CB 2
#define CS 2048
#define CD 768
#define CH 12
#define CDK 64
#define CBH 24
#define CM 4096
#define BHS 49152
#define OUT_ELEMS 3145728

typedef unsigned int u32; typedef unsigned short u16;

__device__ float  g_Q[BHS * CDK];
__device__ float  g_K[BHS * CDK];
__device__ float  g_Vt[(size_t)CBH * CDK * CS];
__device__ float  g_ctx[(size_t)CM * CD];
__device__ float2 g_part[(size_t)BHS * 32];
__device__ float2 g_stats[BHS];

// ---------------- SMEM layout (bytes) ----------------
// A tiles: 128 rows x 72 bf16 (stride 144B) ; B tiles: 64 rows x 72 bf16
#define LDAB 72
#define OFF_AH 0u
#define OFF_AL 18432u
#define OFF_BH 36864u
#define OFF_BL 46080u
#define OFF_EXTRA 55296u
#define SMEM_BYTES (55296 + 1024)
#define STAGE_LD 65

// ---------------- helpers ----------------
__device__ __forceinline__ u32 smem_u32(const void* p) {
    u32 a;
    asm("{ .reg .u64 t; cvta.to.shared.u64 t, %1; cvt.u32.u64 %0, t; }" : "=r"(a) : "l"(p));
    return a;
}
__device__ __forceinline__ u32 cvt2(float a, float b) {  // a->low16, b->high16
    u32 r; asm("cvt.rn.bf16x2.f32 %0, %1, %2;" : "=r"(r) : "f"(b), "f"(a)); return r;
}
__device__ __forceinline__ void split_pair(float a, float b, u32& hi, u32& lo) {
    hi = cvt2(a, b);
    float ra = a - __uint_as_float(hi << 16);
    float rb = b - __uint_as_float(hi & 0xffff0000u);
    lo = cvt2(ra, rb);
}
__device__ __forceinline__ void ldm_x4(u32 addr, u32& r0, u32& r1, u32& r2, u32& r3) {
    asm volatile("ldmatrix.sync.aligned.m8n8.x4.shared.b16 {%0,%1,%2,%3}, [%4];"
                 : "=r"(r0), "=r"(r1), "=r"(r2), "=r"(r3) : "r"(addr));
}
__device__ __forceinline__ void mma16816(float* c, const u32* a, u32 b0, u32 b1) {
    asm volatile("mma.sync.aligned.m16n8k16.row.col.f32.bf16.bf16.f32 "
                 "{%0,%1,%2,%3}, {%4,%5,%6,%7}, {%8,%9}, {%0,%1,%2,%3};"
                 : "+f"(c[0]), "+f"(c[1]), "+f"(c[2]), "+f"(c[3])
                 : "r"(a[0]), "r"(a[1]), "r"(a[2]), "r"(a[3]), "r"(b0), "r"(b1));
}

// fp32 [rows x 64] (row stride rs) -> bf16 hi/lo tiles, padded stride LDAB
__device__ __forceinline__ void fill_split(char* sp, u32 offH, u32 offL,
        const float* __restrict__ src, int rows, int rs, int tid) {
    const int total = rows * 8;
    for (int idx = tid; idx < total; idx += 256) {
        int r = idx >> 3, c = (idx & 7) * 8;
        const float* p = src + (size_t)r * rs + c;
        float4 v0 = *(const float4*)p;
        float4 v1 = *(const float4*)(p + 4);
        uint4 hv, lv;
        split_pair(v0.x, v0.y, hv.x, lv.x);
        split_pair(v0.z, v0.w, hv.y, lv.y);
        split_pair(v1.x, v1.y, hv.z, lv.z);
        split_pair(v1.z, v1.w, hv.w, lv.w);
        u32 off = (u32)(r * (LDAB * 2) + c * 2);
        *(uint4*)(sp + offH + off) = hv;
        *(uint4*)(sp + offL + off) = lv;
    }
}

// one 64-deep k-chunk of the 128x64 block tile, bf16x3 (hh + hl + lh)
__device__ __forceinline__ void gemm_chunk(u32 sb, int wid, int lane, float (*acc)[4][4]) {
    const int MW = (wid >> 1) * 32, NW = (wid & 1) * 32;
    const u32 aRow = lane & 15;
    const u32 aCol = (lane >> 4) * 8;
    const u32 bRow = ((lane >> 4) << 3) + (lane & 7);
    const u32 bCol = ((lane >> 3) & 1) * 8;
#pragma unroll
    for (int ks = 0; ks < 4; ks++) {
        const u32 kb = ks * 16;
        u32 ah[2][4], al[2][4], bh[2][4], bl[2][4];
#pragma unroll
        for (int t = 0; t < 2; t++) {
            u32 ro = (MW + 16 * t + aRow) * (LDAB * 2) + (kb + aCol) * 2;
            ldm_x4(sb + OFF_AH + ro, ah[t][0], ah[t][1], ah[t][2], ah[t][3]);
            ldm_x4(sb + OFF_AL + ro, al[t][0], al[t][1], al[t][2], al[t][3]);
        }
#pragma unroll
        for (int g = 0; g < 2; g++) {
            u32 ro = (NW + 16 * g + bRow) * (LDAB * 2) + (kb + bCol) * 2;
            ldm_x4(sb + OFF_BH + ro, bh[g][0], bh[g][1], bh[g][2], bh[g][3]);
            ldm_x4(sb + OFF_BL + ro, bl[g][0], bl[g][1], bl[g][2], bl[g][3]);
        }
#pragma unroll
        for (int t = 0; t < 2; t++)
#pragma unroll
            for (int u = 0; u < 4; u++) {
                const int g = u >> 1, pr = (u & 1) * 2;
                mma16816(acc[t][u], ah[t], bh[g][pr], bh[g][pr + 1]);
                mma16816(acc[t][u], ah[t], bl[g][pr], bl[g][pr + 1]);
                mma16816(acc[t][u], al[t], bh[g][pr], bh[g][pr + 1]);
            }
    }
}

__device__ __forceinline__ void store_stage(float* stage, float (*acc)[4][4], int wid, int lane) {
    const int MW = (wid >> 1) * 32, NW = (wid & 1) * 32;
    const int r0 = lane >> 2, c0 = (lane & 3) * 2;
#pragma unroll
    for (int t = 0; t < 2; t++)
#pragma unroll
        for (int u = 0; u < 4; u++) {
            float* p0 = stage + (MW + 16 * t + r0) * STAGE_LD + NW + 8 * u + c0;
            p0[0] = acc[t][u][0];
            p0[1] = acc[t][u][1];
            float* p1 = p0 + 8 * STAGE_LD;
            p1[0] = acc[t][u][2];
            p1[1] = acc[t][u][3];
        }
}

// ---------------- Kernel: QKV projection ----------------
__global__ void __launch_bounds__(256) proj_kernel(
    const float* __restrict__ X, const float* __restrict__ W,
    float* __restrict__ O, int vmode)
{
    extern __shared__ char smem[];
    u32 sb = smem_u32(smem);
    const int tid = threadIdx.x, wid = tid >> 5, lane = tid & 31;
    const int n0 = blockIdx.x * 64, m0 = blockIdx.y * 128;

    float acc[2][4][4] = {};
    for (int kc = 0; kc < 12; kc++) {
        __syncthreads();
        fill_split(smem, OFF_AH, OFF_AL, X + (size_t)m0 * CD + kc * 64, 128, CD, tid);
        fill_split(smem, OFF_BH, OFF_BL, W + (size_t)n0 * CD + kc * 64, 64, CD, tid);
        __syncthreads();
        gemm_chunk(sb, wid, lane, acc);
    }
    __syncthreads();
    float* stage = (float*)smem;
    store_stage(stage, acc, wid, lane);
    __syncthreads();

    const int b = m0 >> 11, s0 = m0 & (CS - 1), h = n0 >> 6;
    if (vmode == 0) {
        for (int r = wid; r < 128; r += 8) {
            size_t off = ((size_t)((b * CH + h) * CS + s0 + r)) * CDK;
            O[off + lane]      = stage[r * STAGE_LD + lane];
            O[off + 32 + lane] = stage[r * STAGE_LD + 32 + lane];
        }
    } else {
        for (int c = wid; c < 64; c += 8) {
            size_t off = ((size_t)((b * CH + h) * CDK + c)) * CS + s0;
#pragma unroll
            for (int j = 0; j < 4; j++) {
                int rr = lane + 32 * j;
                O[off + rr] = stage[rr * STAGE_LD + c];
            }
        }
    }
}

// ---------------- Kernel: scores + fused softmax partials ----------------
__global__ void __launch_bounds__(256) scores_kernel(
    const float* __restrict__ Q, const float* __restrict__ K,
    const float* __restrict__ pos_bias, const int* __restrict__ mask,
    float* __restrict__ raw, float2* __restrict__ part)
{
    extern __shared__ char smem[];
    u32 sb = smem_u32(smem);
    const int tid = threadIdx.x, wid = tid >> 5, lane = tid & 31;
    const int kx = blockIdx.x, kk0 = kx * 64;
    const int q0 = blockIdx.y * 128;
    const int bh = blockIdx.z;
    const int b = bh / CH, h = bh - b * CH;

    float acc[2][4][4] = {};
    fill_split(smem, OFF_AH, OFF_AL, Q + ((size_t)bh * CS + q0) * CDK, 128, CDK, tid);
    fill_split(smem, OFF_BH, OFF_BL, K + ((size_t)bh * CS + kk0) * CDK, 64, CDK, tid);
    __syncthreads();
    gemm_chunk(sb, wid, lane, acc);
    __syncthreads();
    float* stage = (float*)smem;
    store_stage(stage, acc, wid, lane);
    __syncthreads();

    for (int r = wid; r < 128; r += 8) {
        const int q = q0 + r;
        float sc0 = stage[r * STAGE_LD + lane] * 0.125f;
        float sc1 = stage[r * STAGE_LD + 32 + lane] * 0.125f;
        size_t pbo = ((size_t)(h * CS + q)) * CS + kk0;
        size_t mko = ((size_t)(b * CS + q)) * CS + kk0;
        float r0 = (mask[mko + lane] == 0)      ? -1e9f : sc0 + pos_bias[pbo + lane];
        float r1 = (mask[mko + 32 + lane] == 0) ? -1e9f : sc1 + pos_bias[pbo + 32 + lane];
        size_t ro = ((size_t)(bh * CS + q)) * CS + kk0;
        raw[ro + lane]      = r0;
        raw[ro + 32 + lane] = r1;
        float mx = fmaxf(r0, r1);
#pragma unroll
        for (int o = 16; o > 0; o >>= 1) mx = fmaxf(mx, __shfl_xor_sync(0xffffffffu, mx, o));
        float se = __expf(r0 - mx) + __expf(r1 - mx);
#pragma unroll
        for (int o = 16; o > 0; o >>= 1) se += __shfl_xor_sync(0xffffffffu, se, o);
        if (lane == 0) part[((size_t)(bh * CS + q)) * 32 + kx] = make_float2(mx, se);
    }
}

// ---------------- Kernel: reduce partials -> (max, 1/sum) ----------------
__global__ void __launch_bounds__(256) reduce_kernel(
    const float2* __restrict__ part, float2* __restrict__ stats)
{
    const int wid = threadIdx.x >> 5, lane = threadIdx.x & 31;
    const int row = blockIdx.x * 8 + wid;
    float2 p = part[(size_t)row * 32 + lane];
    float M = p.x;
#pragma unroll
    for (int o = 16; o > 0; o >>= 1) M = fmaxf(M, __shfl_xor_sync(0xffffffffu, M, o));
    float s = p.y * __expf(p.x - M);
#pragma unroll
    for (int o = 16; o > 0; o >>= 1) s += __shfl_xor_sync(0xffffffffu, s, o);
    if (lane == 0) stats[row] = make_float2(M, 1.0f / s);
}

// ---------------- Kernel: PV (normalize attn in place, ctx = P.V) ----------------
__global__ void __launch_bounds__(256) pv_kernel(
    float* __restrict__ attn, const float* __restrict__ Vt,
    const float2* __restrict__ stats, float* __restrict__ ctx)
{
    extern __shared__ char smem[];
    u32 sb = smem_u32(smem);
    const int tid = threadIdx.x, wid = tid >> 5, lane = tid & 31;
    const int q0 = blockIdx.x * 128;
    const int bh = blockIdx.y;

    float* smax = (float*)(smem + OFF_EXTRA);
    float* sinv = smax + 128;
    if (tid < 128) {
        float2 st = stats[(size_t)bh * CS + q0 + tid];
        smax[tid] = st.x;
        sinv[tid] = st.y;
    }

    const int rb = tid >> 4, cg = (tid & 15) * 4;
    float acc[2][4][4] = {};
    for (int kc = 0; kc < 32; kc++) {
        __syncthreads();
#pragma unroll
        for (int p = 0; p < 8; p++) {
            int row = p * 16 + rb;
            size_t ao = ((size_t)(bh * CS + q0 + row)) * CS + kc * 64 + cg;
            float4 rv = *(const float4*)(attn + ao);
            float mx = smax[row], iv = sinv[row];
            float4 pw;
            pw.x = __expf(rv.x - mx) * iv;
            pw.y = __expf(rv.y - mx) * iv;
            pw.z = __expf(rv.z - mx) * iv;
            pw.w = __expf(rv.w - mx) * iv;
            *(float4*)(attn + ao) = pw;
            uint2 hv, lv;
            split_pair(pw.x, pw.y, hv.x, lv.x);
            split_pair(pw.z, pw.w, hv.y, lv.y);
            u32 off = (u32)(row * (LDAB * 2) + cg * 2);
            *(uint2*)(smem + OFF_AH + off) = hv;
            *(uint2*)(smem + OFF_AL + off) = lv;
        }
        fill_split(smem, OFF_BH, OFF_BL, Vt + (size_t)bh * CDK * CS + kc * 64, 64, CS, tid);
        __syncthreads();
        gemm_chunk(sb, wid, lane, acc);
    }
    __syncthreads();
    float* stage = (float*)smem;
    store_stage(stage, acc, wid, lane);
    __syncthreads();

    const int b = bh / CH, h = bh - b * CH;
    for (int r = wid; r < 128; r += 8) {
        size_t off = ((size_t)(b * CS + q0 + r)) * CD + h * CDK;
        ctx[off + lane]      = stage[r * STAGE_LD + lane];
        ctx[off + 32 + lane] = stage[r * STAGE_LD + 32 + lane];
    }
}

// ---------------- Kernel: output projection ----------------
__global__ void __launch_bounds__(256) outproj_kernel(
    const float* __restrict__ ctx, const float* __restrict__ W,
    const float* __restrict__ bias, float* __restrict__ out)
{
    extern __shared__ char smem[];
    u32 sb = smem_u32(smem);
    const int tid = threadIdx.x, wid = tid >> 5, lane = tid & 31;
    const int n0 = blockIdx.x * 64, m0 = blockIdx.y * 128;

    float acc[2][4][4] = {};
    for (int kc = 0; kc < 12; kc++) {
        __syncthreads();
        fill_split(smem, OFF_AH, OFF_AL, ctx + (size_t)m0 * CD + kc * 64, 128, CD, tid);
        fill_split(smem, OFF_BH, OFF_BL, W + (size_t)n0 * CD + kc * 64, 64, CD, tid);
        __syncthreads();
        gemm_chunk(sb, wid, lane, acc);
    }
    __syncthreads();
    float* stage = (float*)smem;
    store_stage(stage, acc, wid, lane);
    __syncthreads();

    float b0 = bias[n0 + lane];
    float b1 = bias[n0 + 32 + lane];
    for (int r = wid; r < 128; r += 8) {
        size_t off = (size_t)(m0 + r) * CD + n0;
        out[off + lane]      = stage[r * STAGE_LD + lane] + b0;
        out[off + 32 + lane] = stage[r * STAGE_LD + 32 + lane] + b1;
    }
}

// ---------------------------------------------------------------------------
extern "C" void kernel_launch(void* const* d_in, const int* in_sizes, int n_in,
                              void* d_out, int out_size)
{
    (void)in_sizes; (void)n_in; (void)out_size;
    const float* query    = (const float*)d_in[0];
    const float* key      = (const float*)d_in[1];
    const float* value    = (const float*)d_in[2];
    const int*   mask     = (const int*)d_in[3];
    const float* pos_bias = (const float*)d_in[4];
    const float* Wq       = (const float*)d_in[5];
    const float* Wk       = (const float*)d_in[6];
    const float* Wv       = (const float*)d_in[7];
    const float* Wo       = (const float*)d_in[8];
    const float* bo       = (const float*)d_in[9];

    float* out  = (float*)d_out;
    float* attn = out + OUT_ELEMS;

    float *pQ, *pK, *pVt, *pC;
    float2 *pPart, *pStats;
    cudaGetSymbolAddress((void**)&pQ,  g_Q);
    cudaGetSymbolAddress((void**)&pK,  g_K);
    cudaGetSymbolAddress((void**)&pVt, g_Vt);
    cudaGetSymbolAddress((void**)&pC,  g_ctx);
    cudaGetSymbolAddress((void**)&pPart,  g_part);
    cudaGetSymbolAddress((void**)&pStats, g_stats);

    cudaFuncSetAttribute(proj_kernel,    cudaFuncAttributeMaxDynamicSharedMemorySize, SMEM_BYTES);
    cudaFuncSetAttribute(scores_kernel,  cudaFuncAttributeMaxDynamicSharedMemorySize, SMEM_BYTES);
    cudaFuncSetAttribute(pv_kernel,      cudaFuncAttributeMaxDynamicSharedMemorySize, SMEM_BYTES);
    cudaFuncSetAttribute(outproj_kernel, cudaFuncAttributeMaxDynamicSharedMemorySize, SMEM_BYTES);

    dim3 gProj(CD / 64, CM / 128);             // (12, 32)
    proj_kernel<<<gProj, 256, SMEM_BYTES>>>(query, Wq, pQ,  0);
    proj_kernel<<<gProj, 256, SMEM_BYTES>>>(key,   Wk, pK,  0);
    proj_kernel<<<gProj, 256, SMEM_BYTES>>>(value, Wv, pVt, 1);

    dim3 gScores(CS / 64, CS / 128, CBH);      // (32, 16, 24)
    scores_kernel<<<gScores, 256, SMEM_BYTES>>>(pQ, pK, pos_bias, mask, attn, pPart);

    reduce_kernel<<<BHS / 8, 256>>>(pPart, pStats);

    dim3 gPV(CS / 128, CBH);                   // (16, 24)
    pv_kernel<<<gPV, 256, SMEM_BYTES>>>(attn, pVt, pStats, pC);

    outproj_kernel<<<gProj, 256, SMEM_BYTES>>>(pC, Wo, bo, out);
}